// round 7
// baseline (speedup 1.0000x reference)
#include <cuda_runtime.h>
#include <cuda_bf16.h>
#include <cstdint>

typedef unsigned long long ull;

#define N_NODES 21
#define N_EDGES 23
#define D1 64
#define D2 128
#define G_TOTAL 32768
#define BLOCK 512
#define WPB 16
#define GB 8                // graphs per warp (phase 1)
#define M_TILE 128          // graphs per CTA
#define PADK 136            // padded k-extent (bf16) -> row stride 272 B
#define RSTRIDE (PADK * 2)  // 272 bytes

// ---- shared layout (float indices) ----
#define OFF_C2   0           // float2 (c/2, c/2) x21 -> 42, pad 48
#define OFF_TW   48
#define OFF_TI   112
#define OFF_B2   176         // b2 (128) -> 304
#define OFF_A    304         // A tile 128 x 136 bf16 = 8704 floats
#define OFF_B    (OFF_A + 8704)
#define SMEM_FLOATS (OFF_B + 8704)      // 17712
#define SMEM_BYTES  (SMEM_FLOATS * 4)   // 70848

#define XW_FLOATS (GB * N_NODES * 2)    // 336 per warp (x staging, A region)
#define YW_FLOATS (GB * N_NODES * 2)    // 336 per warp (y staging, B region)

__device__ __forceinline__ ull ffma2(ull a, ull b, ull c) {
    ull d; asm("fma.rn.f32x2 %0, %1, %2, %3;" : "=l"(d) : "l"(a), "l"(b), "l"(c)); return d;
}
__device__ __forceinline__ ull pack2(float lo, float hi) {
    ull d; asm("mov.b64 %0, {%1, %2};" : "=l"(d) : "f"(lo), "f"(hi)); return d;
}
__device__ __forceinline__ void unpack2(ull v, float& lo, float& hi) {
    asm("mov.b64 {%0, %1}, %2;" : "=f"(lo), "=f"(hi) : "l"(v));
}
__device__ __forceinline__ uint32_t cvt_bf16x2(float h, float l) {
    uint32_t r; asm("cvt.rn.bf16x2.f32 %0, %1, %2;" : "=r"(r) : "f"(h), "f"(l)); return r;
}
__device__ __forceinline__ void mma_bf16(float& c0, float& c1, float& c2, float& c3,
                                         uint32_t a0, uint32_t a1, uint32_t a2, uint32_t a3,
                                         uint32_t b0, uint32_t b1) {
    asm("mma.sync.aligned.m16n8k16.row.col.f32.bf16.bf16.f32 "
        "{%0,%1,%2,%3}, {%4,%5,%6,%7}, {%8,%9}, {%0,%1,%2,%3};"
        : "+f"(c0), "+f"(c1), "+f"(c2), "+f"(c3)
        : "r"(a0), "r"(a1), "r"(a2), "r"(a3), "r"(b0), "r"(b1));
}

__device__ __constant__ signed char c_esrc[N_EDGES] =
    {0,1,2,3, 0,5,6,7, 0,9,10,11, 0,13,14,15, 0,17,18,19, 5,9,13};
__device__ __constant__ signed char c_etgt[N_EDGES] =
    {1,2,3,4, 5,6,7,8, 9,10,11,12, 13,14,15,16, 17,18,19,20, 9,13,17};
#define R2C 0.70710678118654752f
#define R3C 0.57735026918962576f
__device__ __constant__ float c_dis[N_NODES] = {
    1.0f, R2C, R2C, R2C, R2C,  R2C, R2C, R2C, R2C,
    R3C, R2C, R2C, R2C,  R3C, R2C, R2C, R2C,  R3C, R2C, R2C, R2C
};

__global__ void __launch_bounds__(BLOCK, 2)
hand_gnn_kernel(const float* __restrict__ x,
                const float* __restrict__ W1,
                const float* __restrict__ b1,
                const float* __restrict__ W2,
                const float* __restrict__ b2,
                float* __restrict__ out)
{
    extern __shared__ float sm[];
    char* smc = (char*)sm;
    const int tid  = threadIdx.x;
    const int w    = tid >> 5;
    const int lane = tid & 31;

    // ---- prolog: tables, c, b2 ----
    if (tid < D2) sm[OFF_B2 + tid] = b2[tid];
    if (tid < N_NODES) {
        const int t = tid;
        const float dt = c_dis[t];
        float* sTw = sm + OFF_TW;  int* sTi = (int*)(sm + OFF_TI);
        sTw[t*3+0] = dt*dt;  sTi[t*3+0] = t;
        int p = 1;
        #pragma unroll
        for (int e = 0; e < N_EDGES; e++)
            if ((int)c_etgt[e] == t) { sTw[t*3+p] = dt*c_dis[(int)c_esrc[e]]; sTi[t*3+p] = (int)c_esrc[e]; p++; }
        for (; p < 3; p++) { sTw[t*3+p] = 0.0f; sTi[t*3+p] = 0; }
        float cs = dt;
        #pragma unroll
        for (int e = 0; e < N_EDGES; e++)
            if ((int)c_esrc[e] == t) cs += c_dis[(int)c_etgt[e]];
        float ch = dt * cs * (1.0f / 42.0f);          // c_t/2 (abs-relu trick)
        ((float2*)(sm + OFF_C2))[t] = make_float2(ch, ch);
    }
    __syncthreads();

    const int g_base = blockIdx.x * M_TILE;
    const int g0w    = g_base + w * GB;

    // ---- phase 1: v[8 graphs][64 feats]; lane owns feature pair (2*lane, 2*lane+1) ----
    float*  sx = sm + OFF_A + w * XW_FLOATS;                    // x staging in A region
    float2* sy = (float2*)(sm + OFF_B) + w * (YW_FLOATS / 2);   // y staging in B region

    {   // coalesced x load: 336 floats / warp
        const float4* xg = (const float4*)(x + (size_t)g0w * N_NODES * 2);
        float4* d = (float4*)sx;
        #pragma unroll
        for (int i = lane; i < XW_FLOATS / 4; i += 32) d[i] = xg[i];
    }
    __syncwarp();

    if (lane < N_NODES) {   // sparse y = A @ x
        const float* sTw = sm + OFF_TW;  const int* sTi = (const int*)(sm + OFF_TI);
        const float tw0 = sTw[lane*3+0]; const int ti0 = sTi[lane*3+0];
        const float tw1 = sTw[lane*3+1]; const int ti1 = sTi[lane*3+1];
        const float tw2 = sTw[lane*3+2]; const int ti2 = sTi[lane*3+2];
        #pragma unroll
        for (int j = 0; j < GB; j++) {
            const float2* xj = (const float2*)(sx + j * N_NODES * 2);
            ull y2;
            y2 = ffma2(pack2(tw0, tw0), *(const ull*)&xj[ti0], 0ull);
            y2 = ffma2(pack2(tw1, tw1), *(const ull*)&xj[ti1], y2);
            y2 = ffma2(pack2(tw2, tw2), *(const ull*)&xj[ti2], y2);
            *(ull*)&sy[j * N_NODES + lane] = y2;
        }
    }
    __syncwarp();

    const ull W10p = pack2(W1[2*lane],      W1[2*lane + 1]);
    const ull W11p = pack2(W1[D1 + 2*lane], W1[D1 + 2*lane + 1]);
    const ull B1p  = pack2(b1[2*lane],      b1[2*lane + 1]);
    const ull ABSM = 0x7FFFFFFF7FFFFFFFull;

    ull vH[GB];
    #pragma unroll
    for (int j = 0; j < GB; j++) vH[j] = 0ull;
    for (int t = 0; t < N_NODES; t++) {
        const ull c2 = ((const ull*)(sm + OFF_C2))[t];
        #pragma unroll
        for (int j = 0; j < GB; j++) {
            float2 yt = sy[j * N_NODES + t];          // broadcast
            ull y0 = pack2(yt.x, yt.x);
            ull y1 = pack2(yt.y, yt.y);
            ull h  = ffma2(y0, W10p, ffma2(y1, W11p, B1p));
            vH[j]  = ffma2(c2, h, ffma2(c2, h & ABSM, vH[j]));
        }
    }
    __syncthreads();   // all x/y consumed -> A/B regions reusable

    // ---- write A tile: row = w*8+j, cols [2l,2l+1]=hi, [64+2l,64+2l+1]=lo ----
    {
        char* A = smc + OFF_A * 4;
        #pragma unroll
        for (int j = 0; j < GB; j++) {
            const int row = w * GB + j;
            float va, vb; unpack2(vH[j], va, vb);     // features 2l, 2l+1
            uint32_t hi2 = cvt_bf16x2(vb, va);
            float hia = __uint_as_float(hi2 << 16);
            float hib = __uint_as_float(hi2 & 0xFFFF0000u);
            uint32_t lo2 = cvt_bf16x2(vb - hib, va - hia);
            *(uint32_t*)(A + row * RSTRIDE + 4 * lane)       = hi2;
            *(uint32_t*)(A + row * RSTRIDE + 128 + 4 * lane) = lo2;
        }
    }

    // ---- build B tile (n-major): B[n][k]: k<64 Wh, k in 64..127 Wl ----
    {
        char* B = smc + OFF_B * 4;
        #pragma unroll
        for (int it = 0; it < 2; it++) {
            const int idx = tid + it * BLOCK;         // 1024 items
            const int fp  = idx >> 5;                 // f pair: f = 2*fp
            const int nb  = idx & 31;                 // n block: n0 = 4*nb
            float4 r0 = *(const float4*)(W2 + (2*fp)     * D2 + 4*nb);
            float4 r1 = *(const float4*)(W2 + (2*fp + 1) * D2 + 4*nb);
            const float e0[4] = {r0.x, r0.y, r0.z, r0.w};
            const float e1[4] = {r1.x, r1.y, r1.z, r1.w};
            #pragma unroll
            for (int nn = 0; nn < 4; nn++) {
                const int n = 4*nb + nn;
                float v0 = e0[nn], v1 = e1[nn];
                uint32_t hi2 = cvt_bf16x2(v1, v0);
                float h0 = __uint_as_float(hi2 << 16);
                float h1 = __uint_as_float(hi2 & 0xFFFF0000u);
                uint32_t lo2 = cvt_bf16x2(v1 - h1, v0 - h0);
                *(uint32_t*)(B + n * RSTRIDE + 4 * fp)       = hi2;
                *(uint32_t*)(B + n * RSTRIDE + 128 + 4 * fp) = lo2;
            }
        }
    }
    __syncthreads();

    // ---- epilogue: warp w -> (row block w>>1, n-half w&1): 16 rows x 64 cols ----
    const int rb    = w >> 1;
    const int nbase = (w & 1) * 64;
    const int r  = lane >> 2;           // 0..7
    const int tq = (lane & 3) * 2;      // 0,2,4,6

    float c[8][4];
    #pragma unroll
    for (int m = 0; m < 8; m++) {
        float2 bb = *(const float2*)(sm + OFF_B2 + nbase + m * 8 + tq);
        c[m][0] = bb.x;  c[m][1] = bb.y;  c[m][2] = bb.x;  c[m][3] = bb.y;
    }

    const char* Arow0 = smc + OFF_A * 4 + (rb * 16 + r) * RSTRIDE;
    const char* Arow8 = Arow0 + 8 * RSTRIDE;
    const char* Bbase = smc + OFF_B * 4;

    #pragma unroll
    for (int s = 0; s < 12; s++) {
        // term 0: Vh x Wh (s=0..3), term 1: Vl x Wh (4..7), term 2: Vh x Wl (8..11)
        const int ks = (s & 3) * 16;
        const int ka = (s < 4) ? ks : ((s < 8) ? (64 + ks) : ks);
        const int kb = (s < 8) ? ks : (64 + ks);
        uint32_t a0 = *(const uint32_t*)(Arow0 + (ka + tq) * 2);
        uint32_t a1 = *(const uint32_t*)(Arow8 + (ka + tq) * 2);
        uint32_t a2 = *(const uint32_t*)(Arow0 + (ka + tq + 8) * 2);
        uint32_t a3 = *(const uint32_t*)(Arow8 + (ka + tq + 8) * 2);
        #pragma unroll
        for (int m = 0; m < 8; m++) {
            const char* Bn = Bbase + (nbase + m * 8 + r) * RSTRIDE;
            uint32_t b0 = *(const uint32_t*)(Bn + (kb + tq) * 2);
            uint32_t b1 = *(const uint32_t*)(Bn + (kb + tq + 8) * 2);
            mma_bf16(c[m][0], c[m][1], c[m][2], c[m][3], a0, a1, a2, a3, b0, b1);
        }
    }

    // ---- store ----
    {
        float* o0 = out + (size_t)(g_base + rb * 16 + r) * D2 + nbase;
        float* o1 = o0 + 8 * D2;
        #pragma unroll
        for (int m = 0; m < 8; m++) {
            *(float2*)(o0 + m * 8 + tq) = make_float2(c[m][0], c[m][1]);
            *(float2*)(o1 + m * 8 + tq) = make_float2(c[m][2], c[m][3]);
        }
    }
}

extern "C" void kernel_launch(void* const* d_in, const int* in_sizes, int n_in,
                              void* d_out, int out_size) {
    const float* x  = (const float*)d_in[0];
    const float* W1 = (const float*)d_in[1];
    const float* b1 = (const float*)d_in[2];
    const float* W2 = (const float*)d_in[3];
    const float* b2 = (const float*)d_in[4];
    float* out = (float*)d_out;

    cudaFuncSetAttribute(hand_gnn_kernel,
                         cudaFuncAttributeMaxDynamicSharedMemorySize, SMEM_BYTES);
    hand_gnn_kernel<<<G_TOTAL / M_TILE, BLOCK, SMEM_BYTES>>>(x, W1, b1, W2, b2, out);
}

// round 8
// speedup vs baseline: 1.4963x; 1.4963x over previous
#include <cuda_runtime.h>
#include <cuda_bf16.h>
#include <cstdint>

typedef unsigned long long ull;

#define N_NODES 21
#define N_EDGES 23
#define D1 64
#define D2 128
#define G_TOTAL 32768
#define WPB 8
#define BLOCK 256
#define GB 16               // graphs per warp
#define M_TILE 128          // graphs per CTA
#define PADK 136            // padded k-extent (bf16) -> row stride 272 B, bank spread 4
#define RSTRIDE (PADK * 2)  // 272 bytes

// ---- shared layout (float indices) ----
#define OFF_C2   0           // float2 (c/2, c/2) x21 -> 42, pad 48
#define OFF_TW   48          // [21][3]
#define OFF_TI   112         // [21][3]
#define OFF_B2   176         // b2 (128) -> 304
#define OFF_A    304         // A tile 128 x 136 bf16 = 8704 floats
#define OFF_B    (OFF_A + 8704)
#define SMEM_FLOATS (OFF_B + 8704)      // 17712
#define SMEM_BYTES  (SMEM_FLOATS * 4)   // 70848

#define XW_FLOATS (GB * N_NODES * 2)    // 672 per warp (x staging, A region)
#define YW_FLOATS (GB * N_NODES * 2)    // 672 per warp (y staging, B region)

__device__ __forceinline__ ull ffma2(ull a, ull b, ull c) {
    ull d; asm("fma.rn.f32x2 %0, %1, %2, %3;" : "=l"(d) : "l"(a), "l"(b), "l"(c)); return d;
}
__device__ __forceinline__ ull pack2(float lo, float hi) {
    ull d; asm("mov.b64 %0, {%1, %2};" : "=l"(d) : "f"(lo), "f"(hi)); return d;
}
__device__ __forceinline__ void unpack2(ull v, float& lo, float& hi) {
    asm("mov.b64 {%0, %1}, %2;" : "=f"(lo), "=f"(hi) : "l"(v));
}
__device__ __forceinline__ uint32_t cvt_bf16x2(float h, float l) {
    uint32_t r; asm("cvt.rn.bf16x2.f32 %0, %1, %2;" : "=r"(r) : "f"(h), "f"(l)); return r;
}
__device__ __forceinline__ uint32_t smem_u32(const void* p) {
    uint32_t a; asm("{ .reg .u64 t; cvta.to.shared.u64 t, %1; cvt.u32.u64 %0, t; }" : "=r"(a) : "l"(p));
    return a;
}
__device__ __forceinline__ void mma_bf16(float& c0, float& c1, float& c2, float& c3,
                                         uint32_t a0, uint32_t a1, uint32_t a2, uint32_t a3,
                                         uint32_t b0, uint32_t b1) {
    asm("mma.sync.aligned.m16n8k16.row.col.f32.bf16.bf16.f32 "
        "{%0,%1,%2,%3}, {%4,%5,%6,%7}, {%8,%9}, {%0,%1,%2,%3};"
        : "+f"(c0), "+f"(c1), "+f"(c2), "+f"(c3)
        : "r"(a0), "r"(a1), "r"(a2), "r"(a3), "r"(b0), "r"(b1));
}
__device__ __forceinline__ void ldm_x4(uint32_t& r0, uint32_t& r1, uint32_t& r2, uint32_t& r3,
                                       uint32_t addr) {
    asm volatile("ldmatrix.sync.aligned.m8n8.x4.shared.b16 {%0,%1,%2,%3}, [%4];"
        : "=r"(r0), "=r"(r1), "=r"(r2), "=r"(r3) : "r"(addr));
}

__device__ __constant__ signed char c_esrc[N_EDGES] =
    {0,1,2,3, 0,5,6,7, 0,9,10,11, 0,13,14,15, 0,17,18,19, 5,9,13};
__device__ __constant__ signed char c_etgt[N_EDGES] =
    {1,2,3,4, 5,6,7,8, 9,10,11,12, 13,14,15,16, 17,18,19,20, 9,13,17};
#define R2C 0.70710678118654752f
#define R3C 0.57735026918962576f
__device__ __constant__ float c_dis[N_NODES] = {
    1.0f, R2C, R2C, R2C, R2C,  R2C, R2C, R2C, R2C,
    R3C, R2C, R2C, R2C,  R3C, R2C, R2C, R2C,  R3C, R2C, R2C, R2C
};

__global__ void __launch_bounds__(BLOCK, 2)
hand_gnn_kernel(const float* __restrict__ x,
                const float* __restrict__ W1,
                const float* __restrict__ b1,
                const float* __restrict__ W2,
                const float* __restrict__ b2,
                float* __restrict__ out)
{
    extern __shared__ float sm[];
    char* smc = (char*)sm;
    const int tid  = threadIdx.x;
    const int w    = tid >> 5;
    const int lane = tid & 31;

    // ---- prefetch W2 into registers (8 independent LDG.128, hidden by phase 1) ----
    float4 rw0[4], rw1[4];
    #pragma unroll
    for (int it = 0; it < 4; it++) {
        const int idx = tid + it * BLOCK;       // 1024 items
        const int fp  = idx >> 5;               // feature pair: f = 2*fp
        const int nb  = idx & 31;               // n block: n0 = 4*nb
        rw0[it] = *(const float4*)(W2 + (2*fp)     * D2 + 4*nb);
        rw1[it] = *(const float4*)(W2 + (2*fp + 1) * D2 + 4*nb);
    }

    // ---- prolog: tables, c, b2 ----
    if (tid < D2) sm[OFF_B2 + tid] = b2[tid];
    if (tid < N_NODES) {
        const int t = tid;
        const float dt = c_dis[t];
        float* sTw = sm + OFF_TW;  int* sTi = (int*)(sm + OFF_TI);
        sTw[t*3+0] = dt*dt;  sTi[t*3+0] = t;
        int p = 1;
        #pragma unroll
        for (int e = 0; e < N_EDGES; e++)
            if ((int)c_etgt[e] == t) { sTw[t*3+p] = dt*c_dis[(int)c_esrc[e]]; sTi[t*3+p] = (int)c_esrc[e]; p++; }
        for (; p < 3; p++) { sTw[t*3+p] = 0.0f; sTi[t*3+p] = 0; }
        float cs = dt;
        #pragma unroll
        for (int e = 0; e < N_EDGES; e++)
            if ((int)c_esrc[e] == t) cs += c_dis[(int)c_etgt[e]];
        float ch = dt * cs * (1.0f / 42.0f);          // c_t/2 (abs-relu trick)
        ((float2*)(sm + OFF_C2))[t] = make_float2(ch, ch);
    }
    __syncthreads();

    const int g_base = blockIdx.x * M_TILE;
    const int g0w    = g_base + w * GB;

    // ---- phase 1: v[16 graphs][64 feats]; lane owns feature pair (2*lane, 2*lane+1) ----
    float*  sx = sm + OFF_A + w * XW_FLOATS;                    // x staging in A region
    float2* sy = (float2*)(sm + OFF_B) + w * (YW_FLOATS / 2);   // y staging in B region

    {   // coalesced x load: 672 floats / warp
        const float4* xg = (const float4*)(x + (size_t)g0w * N_NODES * 2);
        float4* d = (float4*)sx;
        #pragma unroll
        for (int i = lane; i < XW_FLOATS / 4; i += 32) d[i] = xg[i];
    }
    __syncwarp();

    if (lane < N_NODES) {   // sparse y = A @ x
        const float* sTw = sm + OFF_TW;  const int* sTi = (const int*)(sm + OFF_TI);
        const float tw0 = sTw[lane*3+0]; const int ti0 = sTi[lane*3+0];
        const float tw1 = sTw[lane*3+1]; const int ti1 = sTi[lane*3+1];
        const float tw2 = sTw[lane*3+2]; const int ti2 = sTi[lane*3+2];
        #pragma unroll 4
        for (int j = 0; j < GB; j++) {
            const float2* xj = (const float2*)(sx + j * N_NODES * 2);
            ull y2;
            y2 = ffma2(pack2(tw0, tw0), *(const ull*)&xj[ti0], 0ull);
            y2 = ffma2(pack2(tw1, tw1), *(const ull*)&xj[ti1], y2);
            y2 = ffma2(pack2(tw2, tw2), *(const ull*)&xj[ti2], y2);
            *(ull*)&sy[j * N_NODES + lane] = y2;
        }
    }
    __syncwarp();

    const ull W10p = pack2(W1[2*lane],      W1[2*lane + 1]);
    const ull W11p = pack2(W1[D1 + 2*lane], W1[D1 + 2*lane + 1]);
    const ull B1p  = pack2(b1[2*lane],      b1[2*lane + 1]);
    const ull ABSM = 0x7FFFFFFF7FFFFFFFull;

    ull vH[GB];
    #pragma unroll
    for (int j = 0; j < GB; j++) vH[j] = 0ull;
    for (int t = 0; t < N_NODES; t++) {
        const ull c2 = ((const ull*)(sm + OFF_C2))[t];
        #pragma unroll
        for (int j = 0; j < GB; j++) {
            float2 yt = sy[j * N_NODES + t];          // broadcast
            ull y0 = pack2(yt.x, yt.x);
            ull y1 = pack2(yt.y, yt.y);
            ull h  = ffma2(y0, W10p, ffma2(y1, W11p, B1p));
            vH[j]  = ffma2(c2, h, ffma2(c2, h & ABSM, vH[j]));
        }
    }
    __syncthreads();   // all x/y consumed -> A/B regions reusable

    // ---- write A tile: row = w*16+j, cols [2l,2l+1]=hi, [64+2l,64+2l+1]=lo ----
    {
        char* A = smc + OFF_A * 4;
        #pragma unroll 4
        for (int j = 0; j < GB; j++) {
            const int row = w * GB + j;
            float va, vb; unpack2(vH[j], va, vb);     // features 2l, 2l+1
            uint32_t hi2 = cvt_bf16x2(vb, va);
            float hia = __uint_as_float(hi2 << 16);
            float hib = __uint_as_float(hi2 & 0xFFFF0000u);
            uint32_t lo2 = cvt_bf16x2(vb - hib, va - hia);
            *(uint32_t*)(A + row * RSTRIDE + 4 * lane)       = hi2;
            *(uint32_t*)(A + row * RSTRIDE + 128 + 4 * lane) = lo2;
        }
    }

    // ---- write B tile from prefetched registers (n-major): k<64 Wh, 64..127 Wl ----
    {
        char* B = smc + OFF_B * 4;
        #pragma unroll
        for (int it = 0; it < 4; it++) {
            const int idx = tid + it * BLOCK;
            const int fp  = idx >> 5;
            const int nb  = idx & 31;
            const float e0[4] = {rw0[it].x, rw0[it].y, rw0[it].z, rw0[it].w};
            const float e1[4] = {rw1[it].x, rw1[it].y, rw1[it].z, rw1[it].w};
            #pragma unroll
            for (int nn = 0; nn < 4; nn++) {
                const int n = 4*nb + nn;
                float v0 = e0[nn], v1 = e1[nn];       // W2[2fp][n], W2[2fp+1][n]
                uint32_t hi2 = cvt_bf16x2(v1, v0);
                float h0 = __uint_as_float(hi2 << 16);
                float h1 = __uint_as_float(hi2 & 0xFFFF0000u);
                uint32_t lo2 = cvt_bf16x2(v1 - h1, v0 - h0);
                *(uint32_t*)(B + n * RSTRIDE + 4 * fp)       = hi2;
                *(uint32_t*)(B + n * RSTRIDE + 128 + 4 * fp) = lo2;
            }
        }
    }
    __syncthreads();

    // ---- epilogue: out[16x128] = A(16x[Vh|Vl]) x B([Wh|Wl]) 3-term + b2 ----
    const int r  = lane >> 2;           // groupID
    const int tq = (lane & 3) * 2;

    float c[16][4];
    #pragma unroll
    for (int m = 0; m < 16; m++) {
        float2 bb = *(const float2*)(sm + OFF_B2 + m * 8 + tq);
        c[m][0] = bb.x;  c[m][1] = bb.y;  c[m][2] = bb.x;  c[m][3] = bb.y;
    }

    // per-lane ldmatrix base addresses (tile = lane>>3: 0:r0 1:r1 2:r2 3:r3)
    const uint32_t smb = smem_u32(sm);
    const int tile = lane >> 3, lr = lane & 7;
    const uint32_t aBase = smb + OFF_A * 4
        + (uint32_t)((w * GB + (tile & 1) * 8 + lr) * RSTRIDE + (tile >> 1) * 16);
    const uint32_t bBase = smb + OFF_B * 4
        + (uint32_t)(((tile & 1) * 8 + lr) * RSTRIDE + (tile >> 1) * 16);

    #pragma unroll
    for (int s = 0; s < 12; s++) {
        // term 0: Vh x Wh (s=0..3), term 1: Vl x Wh (4..7), term 2: Vh x Wl (8..11)
        const int ks = (s & 3) * 16;
        const int ka = (s < 4) ? ks : ((s < 8) ? (64 + ks) : ks);
        const int kb = (s < 8) ? ks : (64 + ks);
        uint32_t a0, a1, a2, a3;
        ldm_x4(a0, a1, a2, a3, aBase + ka * 2);
        #pragma unroll
        for (int mp = 0; mp < 8; mp++) {
            uint32_t b0e, b0o, b1e, b1o;
            ldm_x4(b0e, b0o, b1e, b1o, bBase + (uint32_t)(mp * 16 * RSTRIDE + kb * 2));
            mma_bf16(c[2*mp][0],   c[2*mp][1],   c[2*mp][2],   c[2*mp][3],
                     a0, a1, a2, a3, b0e, b1e);
            mma_bf16(c[2*mp+1][0], c[2*mp+1][1], c[2*mp+1][2], c[2*mp+1][3],
                     a0, a1, a2, a3, b0o, b1o);
        }
    }

    // ---- store ----
    {
        float* o0 = out + (size_t)(g0w + r) * D2;
        float* o1 = o0 + 8 * D2;
        #pragma unroll
        for (int m = 0; m < 16; m++) {
            *(float2*)(o0 + m * 8 + tq) = make_float2(c[m][0], c[m][1]);
            *(float2*)(o1 + m * 8 + tq) = make_float2(c[m][2], c[m][3]);
        }
    }
}

extern "C" void kernel_launch(void* const* d_in, const int* in_sizes, int n_in,
                              void* d_out, int out_size) {
    const float* x  = (const float*)d_in[0];
    const float* W1 = (const float*)d_in[1];
    const float* b1 = (const float*)d_in[2];
    const float* W2 = (const float*)d_in[3];
    const float* b2 = (const float*)d_in[4];
    float* out = (float*)d_out;

    cudaFuncSetAttribute(hand_gnn_kernel,
                         cudaFuncAttributeMaxDynamicSharedMemorySize, SMEM_BYTES);
    hand_gnn_kernel<<<G_TOTAL / M_TILE, BLOCK, SMEM_BYTES>>>(x, W1, b1, W2, b2, out);
}